// round 16
// baseline (speedup 1.0000x reference)
#include <cuda_runtime.h>
#include <cuda_fp16.h>
#include <math.h>
#include <stdint.h>

#define NB 2
#define NC 256
#define HW 4096
#define HW2 (HW * HW)

// L in [-5,5] quantized to u16 with step 10/65536
#define ENCK 6553.6f
#define DECK2 3.0517578125e-4f            /* 20/65536 exact */
#define DECK2L 4.402823871e-4f            /* DECK2 * log2(e) */
#define BIAS2 (-28.85390082f)             /* -20 * log2(e) */

// ---------------- scratch (static __device__ globals; no allocations) ----------------
__device__ uint16_t g_Q[(size_t)NB * HW2];      // quantized logits (67 MB)
__device__ float g_sp[NB * 32 * HW];            // per (row, col-tile) partial sum of exp(L-5)
__device__ float g_zs[NB * HW];                 // 1 / Z
__device__ float g_lz[NB * HW];                 // BIAS2 + log2(1/Z)
__device__ float g_S[NB * HW];                  // row sum of x_c
__device__ float g_lw[NB * HW];                 // BIAS2 + log2(z/(S+1e-8))
__device__ __half g_xh[(size_t)NB * HW * NC];   // normalized fp16, [pixel][chan]

// ---------------- ptx helpers ----------------
static __device__ __forceinline__ uint32_t s2u(const void* p) {
    uint32_t a;
    asm("{ .reg .u64 t; cvta.to.shared.u64 t, %1; cvt.u32.u64 %0, t; }" : "=r"(a) : "l"(p));
    return a;
}
static __device__ __forceinline__ void cpa16(uint32_t dst, const void* src) {
    asm volatile("cp.async.cg.shared.global [%0], [%1], 16;" :: "r"(dst), "l"(src));
}
static __device__ __forceinline__ void ldm4(uint32_t* r, uint32_t a) {
    asm volatile("ldmatrix.sync.aligned.m8n8.x4.shared.b16 {%0,%1,%2,%3}, [%4];"
        : "=r"(r[0]), "=r"(r[1]), "=r"(r[2]), "=r"(r[3]) : "r"(a));
}
static __device__ __forceinline__ void mma16816(float* c, const uint32_t* a,
                                                uint32_t b0, uint32_t b1) {
    asm volatile("mma.sync.aligned.m16n8k16.row.col.f32.f16.f16.f32 "
        "{%0,%1,%2,%3}, {%4,%5,%6,%7}, {%8,%9}, {%0,%1,%2,%3};"
        : "+f"(c[0]), "+f"(c[1]), "+f"(c[2]), "+f"(c[3])
        : "r"(a[0]), "r"(a[1]), "r"(a[2]), "r"(a[3]), "r"(b0), "r"(b1));
}
static __device__ __forceinline__ uint32_t quant2(float L0, float L1) {
    int q0 = __float2int_rn((L0 + 5.0f) * ENCK);
    int q1 = __float2int_rn((L1 + 5.0f) * ENCK);
    q0 = min(max(q0, 0), 65535);
    q1 = min(max(q1, 0), 65535);
    return (uint32_t)q0 | ((uint32_t)q1 << 16);
}

// ---------------- K1: fused normalize + fp16 + transpose -> [p][c] ----------
__global__ __launch_bounds__(256) void normprep_kernel(const float* __restrict__ x) {
    __shared__ float sh[256 * 33];     // sh[c*33 + p]
    __shared__ float ssum[32][9];
    __shared__ float sinv[32];
    int p0 = blockIdx.x * 32, b = blockIdx.y;
    int tid = threadIdx.x;
    int tx = tid & 31, ty = tid >> 5;
    const float* xb = x + (size_t)b * NC * HW;
#pragma unroll
    for (int i = 0; i < 32; ++i) {
        int c = i * 8 + ty;
        sh[c * 33 + tx] = xb[(size_t)c * HW + p0 + tx];
    }
    __syncthreads();
    float s = 0.f;
#pragma unroll
    for (int j = 0; j < 32; ++j) {
        float v = sh[(ty * 32 + j) * 33 + tx];
        s += v * v;
    }
    ssum[tx][ty] = s;
    __syncthreads();
    if (tid < 32) {
        float t = 0.f;
#pragma unroll
        for (int k = 0; k < 8; ++k) t += ssum[tid][k];
        sinv[tid] = 1.0f / fmaxf(sqrtf(t), 1e-12f);
    }
    __syncthreads();
#pragma unroll
    for (int i = 0; i < 32; ++i) {
        int c = tid, pl = i;
        float v = sh[c * 33 + pl] * sinv[pl];
        g_xh[(size_t)(b * HW + p0 + pl) * NC + c] = __float2half_rn(v);
    }
}

// ---------------- K2: symmetric fp16 mma.sync GEMM + fused epilogue ----------
#define AST 144
#define BUF (128 * AST)
#define STAGE (2 * BUF)
#define NCH 4

__global__ __launch_bounds__(256, 2) void gemm_mma_kernel(const float* __restrict__ alpha_p) {
    extern __shared__ char dsm[];
    __shared__ float s_gt[64];
    __shared__ float s_ss[128][2];
    __shared__ float s_css[128][4];

    int tid = threadIdx.x, lane = tid & 31, wid = tid >> 5;
    int b = blockIdx.y;

    // decode upper-triangular tile (rt <= ct)
    int u = 527 - (int)blockIdx.x;
    int i_ = (int)((sqrtf(8.0f * u + 1.0f) - 1.0f) * 0.5f);
    while (i_ * (i_ + 1) / 2 > u) --i_;
    while ((i_ + 1) * (i_ + 2) / 2 <= u) ++i_;
    int j_ = u - i_ * (i_ + 1) / 2;
    int rt = 31 - i_, ct = 31 - j_;
    int row0 = rt * 128, col0 = ct * 128;
    bool mirror = (ct > rt);

    int warp_m = wid & 3, warp_n = wid >> 2;

    if (tid < 64) {
        float d = (float)tid;
        s_gt[tid] = expf(-d * d * (1.0f / (2.0f * 3.2f * 3.2f)));
    }

    const char* xh = (const char*)(g_xh + (size_t)b * HW * NC);
    uint32_t smb = s2u(dsm);

    float acc[2][8][4];
#pragma unroll
    for (int mt = 0; mt < 2; ++mt)
#pragma unroll
        for (int nt = 0; nt < 8; ++nt)
#pragma unroll
            for (int q = 0; q < 4; ++q) acc[mt][nt][q] = 0.f;

    // ---- prologue: load chunk 0 into stage 0 ----
#pragma unroll
    for (int i = 0; i < 8; ++i) {
        int buf = i >> 2;                       // 0=A(row0), 1=B(col0)
        int rem = ((i & 3) << 8) + tid;
        int r = rem >> 3, cc = rem & 7;
        uint32_t so = (uint32_t)(buf * BUF + r * AST + cc * 16);
        size_t go = (size_t)((buf ? col0 : row0) + r) * 512 + cc * 16;
        cpa16(smb + so, xh + go);
    }
    asm volatile("cp.async.commit_group;" ::: "memory");

    int grp = lane >> 3, rr8 = lane & 7;
    int aro = ((grp & 1) << 3) + rr8;
    int ako = (grp & 2) << 3;
    int bro = ((grp >> 1) << 3) + rr8;
    int bko = (grp & 1) << 4;

    for (int ch = 0; ch < NCH; ++ch) {
        asm volatile("cp.async.wait_group 0;" ::: "memory");
        __syncthreads();
        if (ch < NCH - 1) {
            uint32_t sb = smb + ((ch + 1) & 1) * STAGE;
            int kof = (ch + 1) * 128;
#pragma unroll
            for (int i = 0; i < 8; ++i) {
                int buf = i >> 2;
                int rem = ((i & 3) << 8) + tid;
                int r = rem >> 3, cc = rem & 7;
                uint32_t so = (uint32_t)(buf * BUF + r * AST + cc * 16);
                size_t go = (size_t)((buf ? col0 : row0) + r) * 512 + kof + cc * 16;
                cpa16(sb + so, xh + go);
            }
            asm volatile("cp.async.commit_group;" ::: "memory");
        }
        uint32_t sb = smb + (ch & 1) * STAGE;
#pragma unroll
        for (int ks = 0; ks < 4; ++ks) {
            uint32_t ah[2][4];
#pragma unroll
            for (int mt = 0; mt < 2; ++mt) {
                int ar = warp_m * 32 + mt * 16 + aro;
                ldm4(ah[mt], sb + (uint32_t)(ar * AST + ks * 32 + ako));
            }
#pragma unroll
            for (int p = 0; p < 4; ++p) {
                int br = warp_n * 64 + p * 16 + bro;
                uint32_t bh_[4];
                ldm4(bh_, sb + BUF + (uint32_t)(br * AST + ks * 32 + bko));
                mma16816(acc[0][2 * p],     ah[0], bh_[0], bh_[1]);
                mma16816(acc[0][2 * p + 1], ah[0], bh_[2], bh_[3]);
                mma16816(acc[1][2 * p],     ah[1], bh_[0], bh_[1]);
                mma16816(acc[1][2 * p + 1], ah[1], bh_[2], bh_[3]);
            }
        }
    }
    __syncthreads();   // stage buffers dead; s_tq may alias dsm

    // ---- epilogue (fixed-shift softmax: P = exp(L-5), no maxes) ----
    float alpha = *alpha_p;
    int g = lane >> 2, c4 = lane & 3;
    uint16_t* Qout = g_Q + (size_t)b * HW2;
    uint16_t* s_tq = (uint16_t*)dsm;   // [128][130] quantized staging (33.3 KB)

    // 1) L -> quantized store; pv = exp(L-5) kept in acc
#pragma unroll
    for (int mt = 0; mt < 2; ++mt)
#pragma unroll
        for (int half = 0; half < 2; ++half) {
            int rloc = warp_m * 32 + mt * 16 + half * 8 + g;
            int srow = row0 + rloc;
            int sr = srow >> 6, sc = srow & 63;
#pragma unroll
            for (int nt = 0; nt < 8; ++nt) {
                int cbase = warp_n * 64 + nt * 8 + (c4 << 1);
                float Lv[2];
#pragma unroll
                for (int h = 0; h < 2; ++h) {
                    int tcol = col0 + cbase + h;
                    int tr = tcol >> 6, tc = tcol & 63;
                    int dr = sr - tr; dr = dr < 0 ? -dr : dr;
                    int dc = sc - tc; dc = dc < 0 ? -dc : dc;
                    float L = acc[mt][nt][half * 2 + h] * alpha
                              * (1.0f - s_gt[dr] * s_gt[dc]);
                    Lv[h] = L;
                    acc[mt][nt][half * 2 + h] = __expf(L - 5.0f);
                }
                uint32_t qp = quant2(Lv[0], Lv[1]);
                *(uint32_t*)&Qout[(size_t)srow * HW + col0 + cbase] = qp;
                if (mirror)
                    *(uint32_t*)&s_tq[rloc * 130 + cbase] = qp;
            }
        }

    // 2) row partial sums of P
#pragma unroll
    for (int mt = 0; mt < 2; ++mt)
#pragma unroll
        for (int half = 0; half < 2; ++half) {
            int rloc = warp_m * 32 + mt * 16 + half * 8 + g;
            float rs = 0.f;
#pragma unroll
            for (int nt = 0; nt < 8; ++nt)
                rs += acc[mt][nt][half * 2] + acc[mt][nt][half * 2 + 1];
            rs += __shfl_xor_sync(0xFFFFFFFFu, rs, 1);
            rs += __shfl_xor_sync(0xFFFFFFFFu, rs, 2);
            if (c4 == 0) s_ss[rloc][warp_n] = rs;
        }

    // 3) column partial sums (mirror only)
    if (mirror) {
#pragma unroll
        for (int nt = 0; nt < 8; ++nt)
#pragma unroll
            for (int h = 0; h < 2; ++h) {
                float cs = acc[0][nt][h] + acc[0][nt][2 + h]
                         + acc[1][nt][h] + acc[1][nt][2 + h];
                cs += __shfl_xor_sync(0xFFFFFFFFu, cs, 4);
                cs += __shfl_xor_sync(0xFFFFFFFFu, cs, 8);
                cs += __shfl_xor_sync(0xFFFFFFFFu, cs, 16);
                if (g == 0) {
                    int cloc = warp_n * 64 + nt * 8 + (c4 << 1) + h;
                    s_css[cloc][warp_m] = cs;
                }
            }
    }
    __syncthreads();

    if (tid < 128) {
        g_sp[((size_t)b * 32 + ct) * HW + row0 + tid] = s_ss[tid][0] + s_ss[tid][1];
    }
    if (mirror && tid < 128) {
        g_sp[((size_t)b * 32 + rt) * HW + col0 + tid] =
            s_css[tid][0] + s_css[tid][1] + s_css[tid][2] + s_css[tid][3];
    }

    // 4) mirrored quantized store (transposed), coalesced
    if (mirror) {
        for (int i = tid; i < 8192; i += 256) {
            int trow = i >> 6;
            int tc2 = (i & 63) << 1;
            uint32_t q0 = s_tq[tc2 * 130 + trow];
            uint32_t q1 = s_tq[(tc2 + 1) * 130 + trow];
            *(uint32_t*)&Qout[(size_t)(col0 + trow) * HW + row0 + tc2] = q0 | (q1 << 16);
        }
    }
}

// ---------------- K3: combine per-tile partials -> 1/Z, log form ----------------
__global__ __launch_bounds__(256) void rowcomb_kernel() {
    int r = blockIdx.x * 256 + threadIdx.x;
    int b = r >> 12, rr = r & (HW - 1);
    float s = 0.f;
#pragma unroll
    for (int ctile = 0; ctile < 32; ++ctile)
        s += g_sp[((size_t)b * 32 + ctile) * HW + rr];
    g_zs[r] = 1.0f / s;
    g_lz[r] = BIAS2 - __log2f(s);
}

// ---------------- branchless top-3 insert ----------------
__device__ __forceinline__ void top3_insert(float v, float& a, float& b, float& c) {
    float m1 = fminf(a, v);
    a = fmaxf(a, v);
    float m2 = fminf(b, m1);
    b = fmaxf(b, m1);
    c = fmaxf(c, m2);
}

// ---------------- decode 8 u16 -> floats (I2F.U16 half-reg selectors) ----------------
__device__ __forceinline__ void dec8(uint4 pk, float* f) {
    f[0] = (float)(uint16_t)pk.x; f[1] = (float)(uint16_t)(pk.x >> 16);
    f[2] = (float)(uint16_t)pk.y; f[3] = (float)(uint16_t)(pk.y >> 16);
    f[4] = (float)(uint16_t)pk.z; f[5] = (float)(uint16_t)(pk.z >> 16);
    f[6] = (float)(uint16_t)pk.w; f[7] = (float)(uint16_t)(pk.w >> 16);
}

// ---------------- K4: stats pass (S + top3), read-only over Q ----------------
__global__ __launch_bounds__(256) void stats_kernel(float* __restrict__ out_val) {
    __shared__ float sS[8], sa[8], sb2[8], sc2[8];
    int r = blockIdx.x, b = r >> 12, sidx = r & (HW - 1);
    int tid = threadIdx.x, lane = tid & 31, wrp = tid >> 5;
    const float* lzB = g_lz + (b << 12);
    float zs = g_zs[r];
    const uint16_t* Qr = g_Q + (size_t)r * HW;

    int i0 = tid * 8, i1 = (256 + tid) * 8;
    uint4 pk0 = *(const uint4*)(Qr + i0);
    uint4 pk1 = *(const uint4*)(Qr + i1);
    float4 la0 = *(const float4*)&lzB[i0];
    float4 la1 = *(const float4*)&lzB[i0 + 4];
    float4 lb0 = *(const float4*)&lzB[i1];
    float4 lb1 = *(const float4*)&lzB[i1 + 4];

    float f0[8], f1[8];
    dec8(pk0, f0);
    dec8(pk1, f1);

    float S = 0.f, t0 = -1.f, t1 = -1.f, t2 = -1.f;
    {
        float u0 = exp2f(fmaf(f0[0], DECK2L, la0.x));
        float u1 = exp2f(fmaf(f0[1], DECK2L, la0.y));
        float u2 = exp2f(fmaf(f0[2], DECK2L, la0.z));
        float u3 = exp2f(fmaf(f0[3], DECK2L, la0.w));
        float u4 = exp2f(fmaf(f0[4], DECK2L, la1.x));
        float u5 = exp2f(fmaf(f0[5], DECK2L, la1.y));
        float u6 = exp2f(fmaf(f0[6], DECK2L, la1.z));
        float u7 = exp2f(fmaf(f0[7], DECK2L, la1.w));
        S += ((u0 + u1) + (u2 + u3)) + ((u4 + u5) + (u6 + u7));
        top3_insert(u0, t0, t1, t2); top3_insert(u1, t0, t1, t2);
        top3_insert(u2, t0, t1, t2); top3_insert(u3, t0, t1, t2);
        top3_insert(u4, t0, t1, t2); top3_insert(u5, t0, t1, t2);
        top3_insert(u6, t0, t1, t2); top3_insert(u7, t0, t1, t2);
    }
    {
        float u0 = exp2f(fmaf(f1[0], DECK2L, lb0.x));
        float u1 = exp2f(fmaf(f1[1], DECK2L, lb0.y));
        float u2 = exp2f(fmaf(f1[2], DECK2L, lb0.z));
        float u3 = exp2f(fmaf(f1[3], DECK2L, lb0.w));
        float u4 = exp2f(fmaf(f1[4], DECK2L, lb1.x));
        float u5 = exp2f(fmaf(f1[5], DECK2L, lb1.y));
        float u6 = exp2f(fmaf(f1[6], DECK2L, lb1.z));
        float u7 = exp2f(fmaf(f1[7], DECK2L, lb1.w));
        S += ((u0 + u1) + (u2 + u3)) + ((u4 + u5) + (u6 + u7));
        top3_insert(u0, t0, t1, t2); top3_insert(u1, t0, t1, t2);
        top3_insert(u2, t0, t1, t2); top3_insert(u3, t0, t1, t2);
        top3_insert(u4, t0, t1, t2); top3_insert(u5, t0, t1, t2);
        top3_insert(u6, t0, t1, t2); top3_insert(u7, t0, t1, t2);
    }

    // warp reduce
#pragma unroll
    for (int m2 = 1; m2 <= 16; m2 <<= 1) {
        S += __shfl_xor_sync(0xFFFFFFFFu, S, m2);
        float a0 = __shfl_xor_sync(0xFFFFFFFFu, t0, m2);
        float a1 = __shfl_xor_sync(0xFFFFFFFFu, t1, m2);
        float a2 = __shfl_xor_sync(0xFFFFFFFFu, t2, m2);
        top3_insert(a0, t0, t1, t2);
        top3_insert(a1, t0, t1, t2);
        top3_insert(a2, t0, t1, t2);
    }
    if (lane == 0) { sS[wrp] = S; sa[wrp] = t0; sb2[wrp] = t1; sc2[wrp] = t2; }
    __syncthreads();
    if (tid == 0) {
        float Sf = sS[0], a = sa[0], bb = sb2[0], cc = sc2[0];
#pragma unroll
        for (int w2 = 1; w2 < 8; ++w2) {
            Sf += sS[w2];
            top3_insert(sa[w2], a, bb, cc);
            top3_insert(sb2[w2], a, bb, cc);
            top3_insert(sc2[w2], a, bb, cc);
        }
        g_S[r] = zs * Sf;
        out_val[(b * 3 + 0) * HW + sidx] = zs * a;
        out_val[(b * 3 + 1) * HW + sidx] = zs * bb;
        out_val[(b * 3 + 2) * HW + sidx] = zs * cc;
    }
}

// ---------------- K4b: lw = BIAS2 + log2(z / (S + 1e-8)) ----------------
__global__ __launch_bounds__(256) void srecip_kernel() {
    int i = blockIdx.x * 256 + threadIdx.x;
    g_lw[i] = BIAS2 + __log2f(g_zs[i] / (g_S[i] + 1e-8f));
}

// ---------------- K5: write scaled x_soft directly (streaming stores) ----------------
__global__ __launch_bounds__(256) void write_kernel(float* __restrict__ out_soft) {
    int r = blockIdx.x, b = r >> 12;
    int tid = threadIdx.x;
    const float* lwB = g_lw + (b << 12);
    float zs = g_zs[r];
    const uint16_t* Qr = g_Q + (size_t)r * HW;
    float* Or = out_soft + (size_t)r * HW;
#pragma unroll
    for (int part = 0; part < 2; ++part) {
        int t0i = (part * 256 + tid) * 8;
        uint4 pk = *(const uint4*)(Qr + t0i);
        float4 w0 = *(const float4*)&lwB[t0i];
        float4 w1 = *(const float4*)&lwB[t0i + 4];
        float f[8];
        dec8(pk, f);
        float4 v0, v1;
        v0.x = exp2f(fmaf(f[0], DECK2L, w0.x)) * zs;
        v0.y = exp2f(fmaf(f[1], DECK2L, w0.y)) * zs;
        v0.z = exp2f(fmaf(f[2], DECK2L, w0.z)) * zs;
        v0.w = exp2f(fmaf(f[3], DECK2L, w0.w)) * zs;
        v1.x = exp2f(fmaf(f[4], DECK2L, w1.x)) * zs;
        v1.y = exp2f(fmaf(f[5], DECK2L, w1.y)) * zs;
        v1.z = exp2f(fmaf(f[6], DECK2L, w1.z)) * zs;
        v1.w = exp2f(fmaf(f[7], DECK2L, w1.w)) * zs;
        __stcs((float4*)&Or[t0i],     v0);
        __stcs((float4*)&Or[t0i + 4], v1);
    }
}

// ---------------- launch ----------------
extern "C" void kernel_launch(void* const* d_in, const int* in_sizes, int n_in,
                              void* d_out, int out_size) {
    const float* x = (const float*)d_in[0];
    const float* alpha = (const float*)d_in[1];
    float* out = (float*)d_out;
    float* out_val = out;                    // (2,3,64,64)
    float* out_soft = out + NB * 3 * HW;     // (2,4096,64,64)

    cudaFuncSetAttribute(gemm_mma_kernel,
                         cudaFuncAttributeMaxDynamicSharedMemorySize, 2 * STAGE);

    normprep_kernel<<<dim3(HW / 32, NB), 256>>>(x);
    gemm_mma_kernel<<<dim3(528, NB), 256, 2 * STAGE>>>(alpha);
    rowcomb_kernel<<<32, 256>>>();
    stats_kernel<<<NB * HW, 256>>>(out_val);
    srecip_kernel<<<32, 256>>>();
    write_kernel<<<NB * HW, 256>>>(out_soft);
}